// round 1
// baseline (speedup 1.0000x reference)
#include <cuda_runtime.h>
#include <cuda_bf16.h>
#include <math_constants.h>

// ---------------- problem constants ----------------
#define NNODES 50000
#define NEDGES 600000
#define C_IN   128
#define C_HID  256
#define C_OUT  47

// ---------------- static scratch (no allocation allowed) ----------------
__device__ __align__(128) float g_agg [(size_t)NNODES * C_HID];   // reused: layer1 (ld128), layer2 (ld256)
__device__ __align__(128) float g_h1  [(size_t)NNODES * C_HID];
__device__ __align__(128) float g_h2  [(size_t)NNODES * C_HID];
__device__ __align__(128) float g_zr  [(size_t)NNODES * 128];     // layer3: cols 0..46 = z, 47..93 = r (ld 128)
__device__ __align__(128) float g_agg3[(size_t)NNODES * 48];      // ld 48
__device__ __align__(128) float g_deg [NNODES];
__device__ __align__(128) float g_inv [NNODES];
__device__ __align__(128) float g_W3  [96 * 256];                 // packed [Wl3; Wr3; pad]
__device__ int g_is64;

// ---------------- helpers ----------------
__device__ __forceinline__ long long get_idx(const void* ei, long long i, int is64) {
    if (is64) return ((const long long*)ei)[i];
    return (long long)((const int*)ei)[i];
}

// detect whether edge_index is int64 (high words all zero) or int32
__global__ void detect_kernel(const int* ei32) {
    int bad = 0;
    for (int i = 2 * threadIdx.x + 1; i < 4096; i += 512) bad |= ei32[i];
    int any = __syncthreads_or(bad);
    if (threadIdx.x == 0) g_is64 = (any == 0) ? 1 : 0;
}

__global__ void zero_kernel(float4* p, long long n4) {
    long long i = blockIdx.x * (long long)blockDim.x + threadIdx.x;
    long long st = gridDim.x * (long long)blockDim.x;
    float4 z = make_float4(0.f, 0.f, 0.f, 0.f);
    for (; i < n4; i += st) p[i] = z;
}

__global__ void deg_kernel(const void* __restrict__ ei, int E, float* __restrict__ deg) {
    int e = blockIdx.x * blockDim.x + threadIdx.x;
    if (e >= E) return;
    int is64 = g_is64;
    long long d = get_idx(ei, (long long)E + e, is64);
    atomicAdd(&deg[d], 1.0f);
}

__global__ void inv_kernel(const float* __restrict__ deg, float* __restrict__ inv, int n) {
    int i = blockIdx.x * blockDim.x + threadIdx.x;
    if (i < n) inv[i] = 1.0f / fmaxf(deg[i], 1.0f);
}

// one warp per edge; lanes cover feature float4s
__global__ void scatter_kernel(const float4* __restrict__ src, int src_ld4,
                               float4* __restrict__ dst, int dst_ld4, int nC4,
                               const void* __restrict__ ei, int E) {
    long long gid = blockIdx.x * (long long)blockDim.x + threadIdx.x;
    int warp = (int)(gid >> 5);
    int lane = (int)(gid & 31);
    if (warp >= E) return;
    int is64 = g_is64;
    long long s = 0, d = 0;
    if (lane == 0) {
        s = get_idx(ei, warp, is64);
        d = get_idx(ei, (long long)E + warp, is64);
    }
    s = __shfl_sync(0xffffffffu, s, 0);
    d = __shfl_sync(0xffffffffu, d, 0);
    const float4* sp = src + (size_t)s * src_ld4;
    float4*       dp = dst + (size_t)d * dst_ld4;
    for (int c = lane; c < nC4; c += 32) {
        float4 v = sp[c];
        asm volatile("red.global.add.v4.f32 [%0], {%1,%2,%3,%4};"
                     :: "l"(dp + c), "f"(v.x), "f"(v.y), "f"(v.z), "f"(v.w)
                     : "memory");
    }
}

// pack [Wl3 (47x256); Wr3 (47x256); zeros (2x256)] into g_W3 (96x256)
__global__ void pack_w3_kernel(const float* __restrict__ Wl3, const float* __restrict__ Wr3,
                               float* __restrict__ W3) {
    int i = blockIdx.x * blockDim.x + threadIdx.x;
    if (i >= 96 * 256) return;
    int row = i >> 8, k = i & 255;
    float v = 0.f;
    if (row < 47)      v = Wl3[row * 256 + k];
    else if (row < 94) v = Wr3[(row - 47) * 256 + k];
    W3[i] = v;
}

// ---------------- fused GEMM ----------------
// C[m,n] = sum_k Acat[m,k] * Bcat[n,k]; Acat = [A1*scaleA | A2] along K, Bcat = [B1 | B2]
// BM=128, BN=64, BK=16, TM=8, TN=4, 256 threads
__global__ void __launch_bounds__(256)
gemm_kernel(const float* __restrict__ A1, int K1, const float* __restrict__ scaleA,
            const float* __restrict__ A2, int K2,
            const float* __restrict__ B1, const float* __restrict__ B2,
            float* __restrict__ C, int ldc, int M, int N, int do_relu) {
    const int K = K1 + K2;
    __shared__ float As[16][128];
    __shared__ float Bs[16][64];

    const int tid = threadIdx.x;
    const int tr = tid / 16;   // row group 0..15
    const int tc = tid % 16;   // col group 0..15
    const int m_base = blockIdx.y * 128;
    const int n_base = blockIdx.x * 64;

    float acc[8][4];
#pragma unroll
    for (int i = 0; i < 8; i++)
#pragma unroll
        for (int j = 0; j < 4; j++) acc[i][j] = 0.f;

    for (int k0 = 0; k0 < K; k0 += 16) {
        // load A tile (128x16): 2 float4 per thread
#pragma unroll
        for (int t = 0; t < 2; t++) {
            int f = tid * 2 + t;
            int row = f >> 2;
            int kk = (f & 3) * 4;
            int mg = m_base + row;
            int kg = k0 + kk;
            float4 v = make_float4(0.f, 0.f, 0.f, 0.f);
            if (mg < M) {
                if (kg < K1) {
                    v = *(const float4*)(A1 + (size_t)mg * K1 + kg);
                    if (scaleA) {
                        float s = scaleA[mg];
                        v.x *= s; v.y *= s; v.z *= s; v.w *= s;
                    }
                } else {
                    v = *(const float4*)(A2 + (size_t)mg * K2 + (kg - K1));
                }
            }
            As[kk + 0][row] = v.x; As[kk + 1][row] = v.y;
            As[kk + 2][row] = v.z; As[kk + 3][row] = v.w;
        }
        // load B tile (64x16): 1 float4 per thread
        {
            int n = tid >> 2;
            int kk = (tid & 3) * 4;
            int ng = n_base + n;
            int kg = k0 + kk;
            float4 v = make_float4(0.f, 0.f, 0.f, 0.f);
            if (ng < N) {
                if (kg < K1) v = *(const float4*)(B1 + (size_t)ng * K1 + kg);
                else         v = *(const float4*)(B2 + (size_t)ng * K2 + (kg - K1));
            }
            Bs[kk + 0][n] = v.x; Bs[kk + 1][n] = v.y;
            Bs[kk + 2][n] = v.z; Bs[kk + 3][n] = v.w;
        }
        __syncthreads();
#pragma unroll
        for (int k = 0; k < 16; k++) {
            float a[8], b[4];
            *(float4*)&a[0] = *(const float4*)&As[k][tr * 8];
            *(float4*)&a[4] = *(const float4*)&As[k][tr * 8 + 4];
            *(float4*)&b[0] = *(const float4*)&Bs[k][tc * 4];
#pragma unroll
            for (int i = 0; i < 8; i++)
#pragma unroll
                for (int j = 0; j < 4; j++)
                    acc[i][j] = fmaf(a[i], b[j], acc[i][j]);
        }
        __syncthreads();
    }

    // epilogue
    const int ng0 = n_base + tc * 4;
#pragma unroll
    for (int i = 0; i < 8; i++) {
        int mg = m_base + tr * 8 + i;
        if (mg >= M || ng0 >= N) continue;
        float4 v = make_float4(acc[i][0], acc[i][1], acc[i][2], acc[i][3]);
        if (do_relu) {
            v.x = fmaxf(v.x, 0.f); v.y = fmaxf(v.y, 0.f);
            v.z = fmaxf(v.z, 0.f); v.w = fmaxf(v.w, 0.f);
        }
        *(float4*)(C + (size_t)mg * ldc + ng0) = v;
    }
}

// ---------------- final: out = log_softmax(agg3*inv + r) ----------------
__global__ void final_kernel(const float* __restrict__ agg3, const float* __restrict__ zr,
                             const float* __restrict__ inv, float* __restrict__ out, int M) {
    int m = blockIdx.x * blockDim.y + threadIdx.y;
    if (m >= M) return;
    int lane = threadIdx.x;
    float im = inv[m];
    float v1 = -CUDART_INF_F, v2 = -CUDART_INF_F;
    if (lane < 47)
        v1 = agg3[(size_t)m * 48 + lane] * im + zr[(size_t)m * 128 + 47 + lane];
    int c2 = lane + 32;
    if (c2 < 47)
        v2 = agg3[(size_t)m * 48 + c2] * im + zr[(size_t)m * 128 + 47 + c2];
    float mx = fmaxf(v1, v2);
#pragma unroll
    for (int o = 16; o > 0; o >>= 1) mx = fmaxf(mx, __shfl_xor_sync(0xffffffffu, mx, o));
    float s = 0.f;
    if (lane < 47) s += expf(v1 - mx);
    if (c2 < 47)   s += expf(v2 - mx);
#pragma unroll
    for (int o = 16; o > 0; o >>= 1) s += __shfl_xor_sync(0xffffffffu, s, o);
    float lse = logf(s);
    if (lane < 47) out[(size_t)m * 47 + lane] = v1 - mx - lse;
    if (c2 < 47)   out[(size_t)m * 47 + c2]   = v2 - mx - lse;
}

// ---------------- launch ----------------
extern "C" void kernel_launch(void* const* d_in, const int* in_sizes, int n_in,
                              void* d_out, int out_size) {
    const float* x   = (const float*)d_in[0];
    const float* Wl1 = (const float*)d_in[1];
    const float* Wr1 = (const float*)d_in[2];
    const float* Wl2 = (const float*)d_in[3];
    const float* Wr2 = (const float*)d_in[4];
    const float* Wl3 = (const float*)d_in[5];
    const float* Wr3 = (const float*)d_in[6];
    const void*  ei  = d_in[7];
    const int E = in_sizes[7] / 2;
    const int M = in_sizes[0] / C_IN;
    float* out = (float*)d_out;

    float *agg, *h1, *h2, *zr, *agg3, *deg, *inv, *W3;
    cudaGetSymbolAddress((void**)&agg,  g_agg);
    cudaGetSymbolAddress((void**)&h1,   g_h1);
    cudaGetSymbolAddress((void**)&h2,   g_h2);
    cudaGetSymbolAddress((void**)&zr,   g_zr);
    cudaGetSymbolAddress((void**)&agg3, g_agg3);
    cudaGetSymbolAddress((void**)&deg,  g_deg);
    cudaGetSymbolAddress((void**)&inv,  g_inv);
    cudaGetSymbolAddress((void**)&W3,   g_W3);

    detect_kernel<<<1, 256>>>((const int*)ei);

    // degree + inverse
    zero_kernel<<<64, 256>>>((float4*)deg, M / 4);
    deg_kernel<<<(E + 255) / 256, 256>>>(ei, E, deg);
    inv_kernel<<<(M + 255) / 256, 256>>>(deg, inv, M);

    const int scat_blocks = (int)(((long long)E * 32 + 255) / 256);
    dim3 gemm_block(256);

    // ---- layer 1: agg(x) 128-wide; h1 = relu([agg*inv | x] @ [Wl1|Wr1]^T) ----
    zero_kernel<<<2048, 256>>>((float4*)agg, (long long)M * C_IN / 4);
    scatter_kernel<<<scat_blocks, 256>>>((const float4*)x, C_IN / 4,
                                         (float4*)agg, C_IN / 4, C_IN / 4, ei, E);
    {
        dim3 grid(C_HID / 64, (M + 127) / 128);
        gemm_kernel<<<grid, gemm_block>>>(agg, C_IN, inv, x, C_IN,
                                          Wl1, Wr1, h1, C_HID, M, C_HID, 1);
    }

    // ---- layer 2: agg(h1) 256-wide; h2 = relu([agg*inv | h1] @ [Wl2|Wr2]^T) ----
    zero_kernel<<<2048, 256>>>((float4*)agg, (long long)M * C_HID / 4);
    scatter_kernel<<<scat_blocks, 256>>>((const float4*)h1, C_HID / 4,
                                         (float4*)agg, C_HID / 4, C_HID / 4, ei, E);
    {
        dim3 grid(C_HID / 64, (M + 127) / 128);
        gemm_kernel<<<grid, gemm_block>>>(agg, C_HID, inv, h1, C_HID,
                                          Wl2, Wr2, h2, C_HID, M, C_HID, 1);
    }

    // ---- layer 3: transform first (47-wide scatter), then log_softmax ----
    pack_w3_kernel<<<96, 256>>>(Wl3, Wr3, W3);
    {
        dim3 grid(96 / 64 + 1, (M + 127) / 128);  // N=96 -> 2 tiles
        gemm_kernel<<<dim3(2, (M + 127) / 128), gemm_block>>>(
            h2, C_HID, (const float*)nullptr, h2, 0,
            W3, (const float*)nullptr, zr, 128, M, 96, 0);
        (void)grid;
    }
    zero_kernel<<<1024, 256>>>((float4*)agg3, (long long)M * 48 / 4);
    scatter_kernel<<<scat_blocks, 256>>>((const float4*)zr, 128 / 4,
                                         (float4*)agg3, 48 / 4, 48 / 4, ei, E);

    {
        dim3 blk(32, 8);
        final_kernel<<<(M + 7) / 8, blk>>>(agg3, zr, inv, out, M);
    }
}

// round 3
// speedup vs baseline: 1.1351x; 1.1351x over previous
#include <cuda_runtime.h>
#include <cstdint>
#include <math_constants.h>

// ---------------- problem constants ----------------
#define NNODES 50000
#define NEDGES 600000
#define C_IN   128
#define C_HID  256
#define C_OUT  47

// ---------------- static scratch (no allocation allowed) ----------------
__device__ __align__(128) float g_agg [(size_t)NNODES * C_HID];
__device__ __align__(128) float g_h1  [(size_t)NNODES * C_HID];
__device__ __align__(128) float g_h2  [(size_t)NNODES * C_HID];
__device__ __align__(128) float g_zr  [(size_t)NNODES * 128];   // cols 0..46 z, 47..93 r
__device__ __align__(128) float g_agg3[(size_t)NNODES * 48];
__device__ __align__(128) float g_deg [NNODES];
__device__ __align__(128) float g_inv [NNODES];
__device__ __align__(128) float g_W3  [96 * 256];
__device__ int g_is64;

// ---------------- small helpers ----------------
__device__ __forceinline__ long long get_idx(const void* ei, long long i, int is64) {
    if (is64) return ((const long long*)ei)[i];
    return (long long)((const int*)ei)[i];
}

__global__ void detect_kernel(const int* ei32) {
    int bad = 0;
    for (int i = 2 * threadIdx.x + 1; i < 4096; i += 512) bad |= ei32[i];
    int any = __syncthreads_or(bad);
    if (threadIdx.x == 0) g_is64 = (any == 0) ? 1 : 0;
}

__global__ void zero_kernel(float4* p, long long n4) {
    long long i = blockIdx.x * (long long)blockDim.x + threadIdx.x;
    long long st = gridDim.x * (long long)blockDim.x;
    float4 z = make_float4(0.f, 0.f, 0.f, 0.f);
    for (; i < n4; i += st) p[i] = z;
}

__global__ void deg_kernel(const void* __restrict__ ei, int E, float* __restrict__ deg) {
    int e = blockIdx.x * blockDim.x + threadIdx.x;
    if (e >= E) return;
    int is64 = g_is64;
    long long d = get_idx(ei, (long long)E + e, is64);
    atomicAdd(&deg[d], 1.0f);
}

__global__ void inv_kernel(const float* __restrict__ deg, float* __restrict__ inv, int n) {
    int i = blockIdx.x * blockDim.x + threadIdx.x;
    if (i < n) inv[i] = 1.0f / fmaxf(deg[i], 1.0f);
}

// one warp per edge; lanes cover feature float4s
__global__ void scatter_kernel(const float4* __restrict__ src, int src_ld4,
                               float4* __restrict__ dst, int dst_ld4, int nC4,
                               const void* __restrict__ ei, int E) {
    long long gid = blockIdx.x * (long long)blockDim.x + threadIdx.x;
    int warp = (int)(gid >> 5);
    int lane = (int)(gid & 31);
    if (warp >= E) return;
    int is64 = g_is64;
    long long s = 0, d = 0;
    if (lane == 0) {
        s = get_idx(ei, warp, is64);
        d = get_idx(ei, (long long)E + warp, is64);
    }
    s = __shfl_sync(0xffffffffu, s, 0);
    d = __shfl_sync(0xffffffffu, d, 0);
    const float4* sp = src + (size_t)s * src_ld4;
    float4*       dp = dst + (size_t)d * dst_ld4;
    for (int c = lane; c < nC4; c += 32) {
        float4 v = sp[c];
        asm volatile("red.global.add.v4.f32 [%0], {%1,%2,%3,%4};"
                     :: "l"(dp + c), "f"(v.x), "f"(v.y), "f"(v.z), "f"(v.w)
                     : "memory");
    }
}

__global__ void pack_w3_kernel(const float* __restrict__ Wl3, const float* __restrict__ Wr3,
                               float* __restrict__ W3) {
    int i = blockIdx.x * blockDim.x + threadIdx.x;
    if (i >= 96 * 256) return;
    int row = i >> 8, k = i & 255;
    float v = 0.f;
    if (row < 47)      v = Wl3[row * 256 + k];
    else if (row < 94) v = Wr3[(row - 47) * 256 + k];
    W3[i] = v;
}

// ---------------- tf32x3 warp-MMA GEMM ----------------
// C[m,n] = sum_k Acat[m,k]*Bcat[n,k]; Acat = [A1*scaleA | A2], Bcat = [B1 | B2]
// BM=128, BN=128, BK=16. 8 warps in 4(M) x 2(N); warp tile 32x64.
// 3xTF32: hi*hi + hi*lo + lo*hi with fp32 accumulate.

#define LDSROW 20   // 16 + 4 pad floats

__device__ __forceinline__ uint32_t tf32_hi(float v) {
    uint32_t h;
    asm("cvt.rna.satfinite.tf32.f32 %0, %1;" : "=r"(h) : "f"(v));
    return h;
}

__device__ __forceinline__ void mma_tf32(float* c, uint32_t a0, uint32_t a1, uint32_t a2, uint32_t a3,
                                         uint32_t b0, uint32_t b1) {
    asm volatile(
        "mma.sync.aligned.m16n8k8.row.col.f32.tf32.tf32.f32 "
        "{%0,%1,%2,%3}, {%4,%5,%6,%7}, {%8,%9}, {%0,%1,%2,%3};"
        : "+f"(c[0]), "+f"(c[1]), "+f"(c[2]), "+f"(c[3])
        : "r"(a0), "r"(a1), "r"(a2), "r"(a3), "r"(b0), "r"(b1));
}

__global__ void __launch_bounds__(256, 2)
gemm_mma(const float* __restrict__ A1, int K1, const float* __restrict__ scaleA,
         const float* __restrict__ A2, int K2,
         const float* __restrict__ B1, const float* __restrict__ B2,
         float* __restrict__ C, int ldc, int M, int N, int do_relu) {
    __shared__ float Ah[128 * LDSROW];
    __shared__ float Al[128 * LDSROW];
    __shared__ float Bh[128 * LDSROW];
    __shared__ float Bl[128 * LDSROW];

    const int tid = threadIdx.x;
    const int wid = tid >> 5;
    const int lid = tid & 31;
    const int gID = lid >> 2;     // group id 0..7
    const int tig = lid & 3;      // thread in group 0..3
    const int warp_m = wid & 3;   // 0..3 -> 32-row slab
    const int warp_n = wid >> 2;  // 0..1 -> 64-col slab
    const int m_base = blockIdx.y * 128;
    const int n_base = blockIdx.x * 128;
    const int K = K1 + K2;

    float acc[2][8][4];
#pragma unroll
    for (int mi = 0; mi < 2; mi++)
#pragma unroll
        for (int ni = 0; ni < 8; ni++)
#pragma unroll
            for (int j = 0; j < 4; j++) acc[mi][ni][j] = 0.f;

    for (int kg0 = 0; kg0 < K; kg0 += 16) {
        // ---- load + split A tile (128 x 16) ----
        {
            const float* Asrc; int lda; const float* sc = nullptr;
            if (kg0 < K1) { Asrc = A1 + kg0; lda = K1; sc = scaleA; }
            else          { Asrc = A2 + (kg0 - K1); lda = K2; }
#pragma unroll
            for (int t = 0; t < 2; t++) {
                int idx = t * 256 + tid;
                int row = idx >> 2, c4 = (idx & 3) * 4;
                int mg = m_base + row;
                float4 v = make_float4(0.f, 0.f, 0.f, 0.f);
                if (mg < M) {
                    v = *(const float4*)(Asrc + (size_t)mg * lda + c4);
                    if (sc) { float s = sc[mg]; v.x *= s; v.y *= s; v.z *= s; v.w *= s; }
                }
                float hx = __uint_as_float(tf32_hi(v.x));
                float hy = __uint_as_float(tf32_hi(v.y));
                float hz = __uint_as_float(tf32_hi(v.z));
                float hw = __uint_as_float(tf32_hi(v.w));
                int o = row * LDSROW + c4;
                Ah[o + 0] = hx; Ah[o + 1] = hy; Ah[o + 2] = hz; Ah[o + 3] = hw;
                Al[o + 0] = v.x - hx; Al[o + 1] = v.y - hy;
                Al[o + 2] = v.z - hz; Al[o + 3] = v.w - hw;
            }
        }
        // ---- load + split B tile (128 x 16) ----
        {
            const float* Bsrc; int ldb;
            if (kg0 < K1) { Bsrc = B1 + kg0; ldb = K1; }
            else          { Bsrc = B2 + (kg0 - K1); ldb = K2; }
#pragma unroll
            for (int t = 0; t < 2; t++) {
                int idx = t * 256 + tid;
                int row = idx >> 2, c4 = (idx & 3) * 4;
                int ng = n_base + row;
                float4 v = make_float4(0.f, 0.f, 0.f, 0.f);
                if (ng < N) v = *(const float4*)(Bsrc + (size_t)ng * ldb + c4);
                float hx = __uint_as_float(tf32_hi(v.x));
                float hy = __uint_as_float(tf32_hi(v.y));
                float hz = __uint_as_float(tf32_hi(v.z));
                float hw = __uint_as_float(tf32_hi(v.w));
                int o = row * LDSROW + c4;
                Bh[o + 0] = hx; Bh[o + 1] = hy; Bh[o + 2] = hz; Bh[o + 3] = hw;
                Bl[o + 0] = v.x - hx; Bl[o + 1] = v.y - hy;
                Bl[o + 2] = v.z - hz; Bl[o + 3] = v.w - hw;
            }
        }
        __syncthreads();

        // ---- MMA over 2 k-steps ----
#pragma unroll
        for (int ks = 0; ks < 2; ks++) {
            const int k0 = ks * 8;
            uint32_t ah[2][4], al[2][4];
#pragma unroll
            for (int mi = 0; mi < 2; mi++) {
                int rm = warp_m * 32 + mi * 16;
                int r0 = (rm + gID) * LDSROW + k0 + tig;
                int r1 = (rm + gID + 8) * LDSROW + k0 + tig;
                ah[mi][0] = __float_as_uint(Ah[r0]);
                ah[mi][1] = __float_as_uint(Ah[r1]);
                ah[mi][2] = __float_as_uint(Ah[r0 + 4]);
                ah[mi][3] = __float_as_uint(Ah[r1 + 4]);
                al[mi][0] = __float_as_uint(Al[r0]);
                al[mi][1] = __float_as_uint(Al[r1]);
                al[mi][2] = __float_as_uint(Al[r0 + 4]);
                al[mi][3] = __float_as_uint(Al[r1 + 4]);
            }
#pragma unroll
            for (int ni = 0; ni < 8; ni++) {
                int nn = warp_n * 64 + ni * 8 + gID;
                int o = nn * LDSROW + k0 + tig;
                uint32_t bh0 = __float_as_uint(Bh[o]);
                uint32_t bh1 = __float_as_uint(Bh[o + 4]);
                uint32_t bl0 = __float_as_uint(Bl[o]);
                uint32_t bl1 = __float_as_uint(Bl[o + 4]);
#pragma unroll
                for (int mi = 0; mi < 2; mi++) {
                    mma_tf32(acc[mi][ni], ah[mi][0], ah[mi][1], ah[mi][2], ah[mi][3], bh0, bh1);
                    mma_tf32(acc[mi][ni], ah[mi][0], ah[mi][1], ah[mi][2], ah[mi][3], bl0, bl1);
                    mma_tf32(acc[mi][ni], al[mi][0], al[mi][1], al[mi][2], al[mi][3], bh0, bh1);
                }
            }
        }
        __syncthreads();
    }

    // ---- epilogue ----
#pragma unroll
    for (int mi = 0; mi < 2; mi++) {
#pragma unroll
        for (int ni = 0; ni < 8; ni++) {
            int col = n_base + warp_n * 64 + ni * 8 + 2 * tig;
            if (col >= N) continue;
            int r0 = m_base + warp_m * 32 + mi * 16 + gID;
            int r1 = r0 + 8;
            float2 v0 = make_float2(acc[mi][ni][0], acc[mi][ni][1]);
            float2 v1 = make_float2(acc[mi][ni][2], acc[mi][ni][3]);
            if (do_relu) {
                v0.x = fmaxf(v0.x, 0.f); v0.y = fmaxf(v0.y, 0.f);
                v1.x = fmaxf(v1.x, 0.f); v1.y = fmaxf(v1.y, 0.f);
            }
            if (r0 < M) *(float2*)(C + (size_t)r0 * ldc + col) = v0;
            if (r1 < M) *(float2*)(C + (size_t)r1 * ldc + col) = v1;
        }
    }
}

// ---------------- final: out = log_softmax(agg3*inv + r) ----------------
__global__ void final_kernel(const float* __restrict__ agg3, const float* __restrict__ zr,
                             const float* __restrict__ inv, float* __restrict__ out, int M) {
    int m = blockIdx.x * blockDim.y + threadIdx.y;
    if (m >= M) return;
    int lane = threadIdx.x;
    float im = inv[m];
    float v1 = -CUDART_INF_F, v2 = -CUDART_INF_F;
    if (lane < 47)
        v1 = agg3[(size_t)m * 48 + lane] * im + zr[(size_t)m * 128 + 47 + lane];
    int c2 = lane + 32;
    if (c2 < 47)
        v2 = agg3[(size_t)m * 48 + c2] * im + zr[(size_t)m * 128 + 47 + c2];
    float mx = fmaxf(v1, v2);
#pragma unroll
    for (int o = 16; o > 0; o >>= 1) mx = fmaxf(mx, __shfl_xor_sync(0xffffffffu, mx, o));
    float s = 0.f;
    if (lane < 47) s += expf(v1 - mx);
    if (c2 < 47)   s += expf(v2 - mx);
#pragma unroll
    for (int o = 16; o > 0; o >>= 1) s += __shfl_xor_sync(0xffffffffu, s, o);
    float lse = logf(s);
    if (lane < 47) out[(size_t)m * 47 + lane] = v1 - mx - lse;
    if (c2 < 47)   out[(size_t)m * 47 + c2]   = v2 - mx - lse;
}

// ---------------- launch ----------------
extern "C" void kernel_launch(void* const* d_in, const int* in_sizes, int n_in,
                              void* d_out, int out_size) {
    const float* x   = (const float*)d_in[0];
    const float* Wl1 = (const float*)d_in[1];
    const float* Wr1 = (const float*)d_in[2];
    const float* Wl2 = (const float*)d_in[3];
    const float* Wr2 = (const float*)d_in[4];
    const float* Wl3 = (const float*)d_in[5];
    const float* Wr3 = (const float*)d_in[6];
    const void*  ei  = d_in[7];
    const int E = in_sizes[7] / 2;
    const int M = in_sizes[0] / C_IN;
    float* out = (float*)d_out;

    float *agg, *h1, *h2, *zr, *agg3, *deg, *inv, *W3;
    cudaGetSymbolAddress((void**)&agg,  g_agg);
    cudaGetSymbolAddress((void**)&h1,   g_h1);
    cudaGetSymbolAddress((void**)&h2,   g_h2);
    cudaGetSymbolAddress((void**)&zr,   g_zr);
    cudaGetSymbolAddress((void**)&agg3, g_agg3);
    cudaGetSymbolAddress((void**)&deg,  g_deg);
    cudaGetSymbolAddress((void**)&inv,  g_inv);
    cudaGetSymbolAddress((void**)&W3,   g_W3);

    detect_kernel<<<1, 256>>>((const int*)ei);

    zero_kernel<<<64, 256>>>((float4*)deg, M / 4);
    deg_kernel<<<(E + 255) / 256, 256>>>(ei, E, deg);
    inv_kernel<<<(M + 255) / 256, 256>>>(deg, inv, M);

    const int scat_blocks = (int)(((long long)E * 32 + 255) / 256);
    const int grid_m = (M + 127) / 128;

    // ---- layer 1 ----
    zero_kernel<<<2048, 256>>>((float4*)agg, (long long)M * C_IN / 4);
    scatter_kernel<<<scat_blocks, 256>>>((const float4*)x, C_IN / 4,
                                         (float4*)agg, C_IN / 4, C_IN / 4, ei, E);
    gemm_mma<<<dim3(2, grid_m), 256>>>(agg, C_IN, inv, x, C_IN,
                                       Wl1, Wr1, h1, C_HID, M, C_HID, 1);

    // ---- layer 2 ----
    zero_kernel<<<2048, 256>>>((float4*)agg, (long long)M * C_HID / 4);
    scatter_kernel<<<scat_blocks, 256>>>((const float4*)h1, C_HID / 4,
                                         (float4*)agg, C_HID / 4, C_HID / 4, ei, E);
    gemm_mma<<<dim3(2, grid_m), 256>>>(agg, C_HID, inv, h1, C_HID,
                                       Wl2, Wr2, h2, C_HID, M, C_HID, 1);

    // ---- layer 3: transform-first ----
    pack_w3_kernel<<<96, 256>>>(Wl3, Wr3, W3);
    gemm_mma<<<dim3(1, grid_m), 256>>>(h2, C_HID, (const float*)nullptr, h2, 0,
                                       W3, (const float*)nullptr, zr, 128, M, 96, 0);
    zero_kernel<<<1024, 256>>>((float4*)agg3, (long long)M * 48 / 4);
    scatter_kernel<<<scat_blocks, 256>>>((const float4*)zr, 128 / 4,
                                         (float4*)agg3, 48 / 4, 48 / 4, ei, E);

    dim3 blk(32, 8);
    final_kernel<<<(M + 7) / 8, blk>>>(agg3, zr, inv, out, M);
}

// round 4
// speedup vs baseline: 1.4003x; 1.2336x over previous
#include <cuda_runtime.h>
#include <cstdint>
#include <math_constants.h>

// ---------------- problem constants ----------------
#define NNODES 50000
#define NEDGES 600000
#define C_IN   128
#define C_HID  256
#define C_OUT  47

// ---------------- static scratch (no allocation allowed) ----------------
__device__ __align__(128) float g_agg [(size_t)NNODES * C_HID];
__device__ __align__(128) float g_h1  [(size_t)NNODES * C_HID];
__device__ __align__(128) float g_h2  [(size_t)NNODES * C_HID];
__device__ __align__(128) float g_zr  [(size_t)NNODES * 128];   // cols 0..46 z, 47..93 r
__device__ __align__(128) float g_agg3[(size_t)NNODES * 48];
__device__ __align__(128) float g_inv [NNODES];
__device__ __align__(128) float g_W3  [96 * 256];
__device__ __align__(128) int   g_cnt [NNODES];
__device__ __align__(128) int   g_rowptr[NNODES + 1];
__device__ __align__(128) int   g_cursor[NNODES];
__device__ __align__(128) int   g_csr [NEDGES];
__device__ int g_is64;

// ---------------- small helpers ----------------
__device__ __forceinline__ long long get_idx(const void* ei, long long i, int is64) {
    if (is64) return ((const long long*)ei)[i];
    return (long long)((const int*)ei)[i];
}

__global__ void detect_kernel(const int* ei32) {
    int bad = 0;
    for (int i = 2 * threadIdx.x + 1; i < 4096; i += 512) bad |= ei32[i];
    int any = __syncthreads_or(bad);
    if (threadIdx.x == 0) g_is64 = (any == 0) ? 1 : 0;
}

__global__ void zero_int_kernel(int* p, int n) {
    int i = blockIdx.x * blockDim.x + threadIdx.x;
    if (i < n) p[i] = 0;
}

__global__ void hist_kernel(const void* __restrict__ ei, int E, int* __restrict__ cnt) {
    int e = blockIdx.x * blockDim.x + threadIdx.x;
    if (e >= E) return;
    int is64 = g_is64;
    long long d = get_idx(ei, (long long)E + e, is64);
    atomicAdd(&cnt[d], 1);
}

// single-block scan: rowptr (exclusive) + inv = 1/max(deg,1)
__global__ void scan_kernel(const int* __restrict__ cnt, int* __restrict__ rowptr,
                            float* __restrict__ inv, int M) {
    __shared__ int ssum[1024];
    int t = threadIdx.x;
    int chunk = (M + 1023) / 1024;
    int b = t * chunk;
    int e = min(M, b + chunk);
    int s = 0;
    for (int i = b; i < e; i++) s += cnt[i];
    ssum[t] = s;
    __syncthreads();
    for (int off = 1; off < 1024; off <<= 1) {
        int v = (t >= off) ? ssum[t - off] : 0;
        __syncthreads();
        ssum[t] += v;
        __syncthreads();
    }
    int base = (t == 0) ? 0 : ssum[t - 1];
    for (int i = b; i < e; i++) {
        rowptr[i] = base;
        int c = cnt[i];
        inv[i] = 1.0f / fmaxf((float)c, 1.0f);
        base += c;
    }
    if (t == 1023) rowptr[M] = base;
}

__global__ void copy_int_kernel(const int* __restrict__ a, int* __restrict__ b, int n) {
    int i = blockIdx.x * blockDim.x + threadIdx.x;
    if (i < n) b[i] = a[i];
}

__global__ void fill_kernel(const void* __restrict__ ei, int E,
                            int* __restrict__ cursor, int* __restrict__ csr) {
    int e = blockIdx.x * blockDim.x + threadIdx.x;
    if (e >= E) return;
    int is64 = g_is64;
    long long s = get_idx(ei, e, is64);
    long long d = get_idx(ei, (long long)E + e, is64);
    int slot = atomicAdd(&cursor[d], 1);
    csr[slot] = (int)s;
}

// ---------------- gather-reduce: one warp per node ----------------
template <int NACC>
__global__ void gather_kernel(const float4* __restrict__ src, int src_ld4,
                              float4* __restrict__ dst, int dst_ld4, int nC4,
                              const int* __restrict__ rowptr, const int* __restrict__ csr,
                              const float* __restrict__ inv, int M) {
    int node = blockIdx.x * (blockDim.x >> 5) + (threadIdx.x >> 5);
    if (node >= M) return;
    int lane = threadIdx.x & 31;
    int beg = rowptr[node], end = rowptr[node + 1];
    float s = inv[node];
    float4 acc[NACC];
    bool act[NACC];
#pragma unroll
    for (int i = 0; i < NACC; i++) {
        acc[i] = make_float4(0.f, 0.f, 0.f, 0.f);
        act[i] = (lane + 32 * i) < nC4;
    }
    int e = beg;
    // unroll-by-2 for MLP
    for (; e + 1 < end; e += 2) {
        const float4* r0 = src + (size_t)csr[e] * src_ld4;
        const float4* r1 = src + (size_t)csr[e + 1] * src_ld4;
#pragma unroll
        for (int i = 0; i < NACC; i++) {
            if (act[i]) {
                float4 v0 = r0[lane + 32 * i];
                float4 v1 = r1[lane + 32 * i];
                acc[i].x += v0.x; acc[i].y += v0.y; acc[i].z += v0.z; acc[i].w += v0.w;
                acc[i].x += v1.x; acc[i].y += v1.y; acc[i].z += v1.z; acc[i].w += v1.w;
            }
        }
    }
    if (e < end) {
        const float4* r0 = src + (size_t)csr[e] * src_ld4;
#pragma unroll
        for (int i = 0; i < NACC; i++) {
            if (act[i]) {
                float4 v0 = r0[lane + 32 * i];
                acc[i].x += v0.x; acc[i].y += v0.y; acc[i].z += v0.z; acc[i].w += v0.w;
            }
        }
    }
    float4* drow = dst + (size_t)node * dst_ld4;
#pragma unroll
    for (int i = 0; i < NACC; i++) {
        if (act[i]) {
            acc[i].x *= s; acc[i].y *= s; acc[i].z *= s; acc[i].w *= s;
            drow[lane + 32 * i] = acc[i];
        }
    }
}

__global__ void pack_w3_kernel(const float* __restrict__ Wl3, const float* __restrict__ Wr3,
                               float* __restrict__ W3) {
    int i = blockIdx.x * blockDim.x + threadIdx.x;
    if (i >= 96 * 256) return;
    int row = i >> 8, k = i & 255;
    float v = 0.f;
    if (row < 47)      v = Wl3[row * 256 + k];
    else if (row < 94) v = Wr3[(row - 47) * 256 + k];
    W3[i] = v;
}

// ---------------- tf32x3 warp-MMA GEMM ----------------
#define LDSROW 20   // 16 + 4 pad floats

__device__ __forceinline__ uint32_t tf32_hi(float v) {
    uint32_t h;
    asm("cvt.rna.satfinite.tf32.f32 %0, %1;" : "=r"(h) : "f"(v));
    return h;
}

__device__ __forceinline__ void mma_tf32(float* c, uint32_t a0, uint32_t a1, uint32_t a2, uint32_t a3,
                                         uint32_t b0, uint32_t b1) {
    asm volatile(
        "mma.sync.aligned.m16n8k8.row.col.f32.tf32.tf32.f32 "
        "{%0,%1,%2,%3}, {%4,%5,%6,%7}, {%8,%9}, {%0,%1,%2,%3};"
        : "+f"(c[0]), "+f"(c[1]), "+f"(c[2]), "+f"(c[3])
        : "r"(a0), "r"(a1), "r"(a2), "r"(a3), "r"(b0), "r"(b1));
}

__global__ void __launch_bounds__(256, 2)
gemm_mma(const float* __restrict__ A1, int K1,
         const float* __restrict__ A2, int K2,
         const float* __restrict__ B1, const float* __restrict__ B2,
         float* __restrict__ C, int ldc, int M, int N, int do_relu) {
    __shared__ float Ah[128 * LDSROW];
    __shared__ float Al[128 * LDSROW];
    __shared__ float Bh[128 * LDSROW];
    __shared__ float Bl[128 * LDSROW];

    const int tid = threadIdx.x;
    const int wid = tid >> 5;
    const int lid = tid & 31;
    const int gID = lid >> 2;
    const int tig = lid & 3;
    const int warp_m = wid & 3;
    const int warp_n = wid >> 2;
    const int m_base = blockIdx.y * 128;
    const int n_base = blockIdx.x * 128;
    const int K = K1 + K2;

    float acc[2][8][4];
#pragma unroll
    for (int mi = 0; mi < 2; mi++)
#pragma unroll
        for (int ni = 0; ni < 8; ni++)
#pragma unroll
            for (int j = 0; j < 4; j++) acc[mi][ni][j] = 0.f;

    for (int kg0 = 0; kg0 < K; kg0 += 16) {
        {
            const float* Asrc; int lda;
            if (kg0 < K1) { Asrc = A1 + kg0; lda = K1; }
            else          { Asrc = A2 + (kg0 - K1); lda = K2; }
#pragma unroll
            for (int t = 0; t < 2; t++) {
                int idx = t * 256 + tid;
                int row = idx >> 2, c4 = (idx & 3) * 4;
                int mg = m_base + row;
                float4 v = make_float4(0.f, 0.f, 0.f, 0.f);
                if (mg < M) v = *(const float4*)(Asrc + (size_t)mg * lda + c4);
                float hx = __uint_as_float(tf32_hi(v.x));
                float hy = __uint_as_float(tf32_hi(v.y));
                float hz = __uint_as_float(tf32_hi(v.z));
                float hw = __uint_as_float(tf32_hi(v.w));
                int o = row * LDSROW + c4;
                Ah[o + 0] = hx; Ah[o + 1] = hy; Ah[o + 2] = hz; Ah[o + 3] = hw;
                Al[o + 0] = v.x - hx; Al[o + 1] = v.y - hy;
                Al[o + 2] = v.z - hz; Al[o + 3] = v.w - hw;
            }
        }
        {
            const float* Bsrc; int ldb;
            if (kg0 < K1) { Bsrc = B1 + kg0; ldb = K1; }
            else          { Bsrc = B2 + (kg0 - K1); ldb = K2; }
#pragma unroll
            for (int t = 0; t < 2; t++) {
                int idx = t * 256 + tid;
                int row = idx >> 2, c4 = (idx & 3) * 4;
                int ng = n_base + row;
                float4 v = make_float4(0.f, 0.f, 0.f, 0.f);
                if (ng < N) v = *(const float4*)(Bsrc + (size_t)ng * ldb + c4);
                float hx = __uint_as_float(tf32_hi(v.x));
                float hy = __uint_as_float(tf32_hi(v.y));
                float hz = __uint_as_float(tf32_hi(v.z));
                float hw = __uint_as_float(tf32_hi(v.w));
                int o = row * LDSROW + c4;
                Bh[o + 0] = hx; Bh[o + 1] = hy; Bh[o + 2] = hz; Bh[o + 3] = hw;
                Bl[o + 0] = v.x - hx; Bl[o + 1] = v.y - hy;
                Bl[o + 2] = v.z - hz; Bl[o + 3] = v.w - hw;
            }
        }
        __syncthreads();

#pragma unroll
        for (int ks = 0; ks < 2; ks++) {
            const int k0 = ks * 8;
            uint32_t ah[2][4], al[2][4];
#pragma unroll
            for (int mi = 0; mi < 2; mi++) {
                int rm = warp_m * 32 + mi * 16;
                int r0 = (rm + gID) * LDSROW + k0 + tig;
                int r1 = (rm + gID + 8) * LDSROW + k0 + tig;
                ah[mi][0] = __float_as_uint(Ah[r0]);
                ah[mi][1] = __float_as_uint(Ah[r1]);
                ah[mi][2] = __float_as_uint(Ah[r0 + 4]);
                ah[mi][3] = __float_as_uint(Ah[r1 + 4]);
                al[mi][0] = __float_as_uint(Al[r0]);
                al[mi][1] = __float_as_uint(Al[r1]);
                al[mi][2] = __float_as_uint(Al[r0 + 4]);
                al[mi][3] = __float_as_uint(Al[r1 + 4]);
            }
#pragma unroll
            for (int ni = 0; ni < 8; ni++) {
                int nn = warp_n * 64 + ni * 8 + gID;
                int o = nn * LDSROW + k0 + tig;
                uint32_t bh0 = __float_as_uint(Bh[o]);
                uint32_t bh1 = __float_as_uint(Bh[o + 4]);
                uint32_t bl0 = __float_as_uint(Bl[o]);
                uint32_t bl1 = __float_as_uint(Bl[o + 4]);
#pragma unroll
                for (int mi = 0; mi < 2; mi++) {
                    mma_tf32(acc[mi][ni], ah[mi][0], ah[mi][1], ah[mi][2], ah[mi][3], bh0, bh1);
                    mma_tf32(acc[mi][ni], ah[mi][0], ah[mi][1], ah[mi][2], ah[mi][3], bl0, bl1);
                    mma_tf32(acc[mi][ni], al[mi][0], al[mi][1], al[mi][2], al[mi][3], bh0, bh1);
                }
            }
        }
        __syncthreads();
    }

#pragma unroll
    for (int mi = 0; mi < 2; mi++) {
#pragma unroll
        for (int ni = 0; ni < 8; ni++) {
            int col = n_base + warp_n * 64 + ni * 8 + 2 * tig;
            if (col >= N) continue;
            int r0 = m_base + warp_m * 32 + mi * 16 + gID;
            int r1 = r0 + 8;
            float2 v0 = make_float2(acc[mi][ni][0], acc[mi][ni][1]);
            float2 v1 = make_float2(acc[mi][ni][2], acc[mi][ni][3]);
            if (do_relu) {
                v0.x = fmaxf(v0.x, 0.f); v0.y = fmaxf(v0.y, 0.f);
                v1.x = fmaxf(v1.x, 0.f); v1.y = fmaxf(v1.y, 0.f);
            }
            if (r0 < M) *(float2*)(C + (size_t)r0 * ldc + col) = v0;
            if (r1 < M) *(float2*)(C + (size_t)r1 * ldc + col) = v1;
        }
    }
}

// ---------------- final: out = log_softmax(agg3*inv + r); inv already applied ----------------
__global__ void final_kernel(const float* __restrict__ agg3, const float* __restrict__ zr,
                             float* __restrict__ out, int M) {
    int m = blockIdx.x * blockDim.y + threadIdx.y;
    if (m >= M) return;
    int lane = threadIdx.x;
    float v1 = -CUDART_INF_F, v2 = -CUDART_INF_F;
    if (lane < 47)
        v1 = agg3[(size_t)m * 48 + lane] + zr[(size_t)m * 128 + 47 + lane];
    int c2 = lane + 32;
    if (c2 < 47)
        v2 = agg3[(size_t)m * 48 + c2] + zr[(size_t)m * 128 + 47 + c2];
    float mx = fmaxf(v1, v2);
#pragma unroll
    for (int o = 16; o > 0; o >>= 1) mx = fmaxf(mx, __shfl_xor_sync(0xffffffffu, mx, o));
    float s = 0.f;
    if (lane < 47) s += expf(v1 - mx);
    if (c2 < 47)   s += expf(v2 - mx);
#pragma unroll
    for (int o = 16; o > 0; o >>= 1) s += __shfl_xor_sync(0xffffffffu, s, o);
    float lse = logf(s);
    if (lane < 47) out[(size_t)m * 47 + lane] = v1 - mx - lse;
    if (c2 < 47)   out[(size_t)m * 47 + c2]   = v2 - mx - lse;
}

// ---------------- launch ----------------
extern "C" void kernel_launch(void* const* d_in, const int* in_sizes, int n_in,
                              void* d_out, int out_size) {
    const float* x   = (const float*)d_in[0];
    const float* Wl1 = (const float*)d_in[1];
    const float* Wr1 = (const float*)d_in[2];
    const float* Wl2 = (const float*)d_in[3];
    const float* Wr2 = (const float*)d_in[4];
    const float* Wl3 = (const float*)d_in[5];
    const float* Wr3 = (const float*)d_in[6];
    const void*  ei  = d_in[7];
    const int E = in_sizes[7] / 2;
    const int M = in_sizes[0] / C_IN;
    float* out = (float*)d_out;

    float *agg, *h1, *h2, *zr, *agg3, *inv, *W3;
    int *cnt, *rowptr, *cursor, *csr;
    cudaGetSymbolAddress((void**)&agg,    g_agg);
    cudaGetSymbolAddress((void**)&h1,     g_h1);
    cudaGetSymbolAddress((void**)&h2,     g_h2);
    cudaGetSymbolAddress((void**)&zr,     g_zr);
    cudaGetSymbolAddress((void**)&agg3,   g_agg3);
    cudaGetSymbolAddress((void**)&inv,    g_inv);
    cudaGetSymbolAddress((void**)&W3,     g_W3);
    cudaGetSymbolAddress((void**)&cnt,    g_cnt);
    cudaGetSymbolAddress((void**)&rowptr, g_rowptr);
    cudaGetSymbolAddress((void**)&cursor, g_cursor);
    cudaGetSymbolAddress((void**)&csr,    g_csr);

    detect_kernel<<<1, 256>>>((const int*)ei);

    // ---- CSR build ----
    zero_int_kernel<<<(M + 255) / 256, 256>>>(cnt, M);
    hist_kernel<<<(E + 255) / 256, 256>>>(ei, E, cnt);
    scan_kernel<<<1, 1024>>>(cnt, rowptr, inv, M);
    copy_int_kernel<<<(M + 255) / 256, 256>>>(rowptr, cursor, M);
    fill_kernel<<<(E + 255) / 256, 256>>>(ei, E, cursor, csr);

    const int gat_blocks = (M + 7) / 8;   // 8 warps (nodes) per block
    const int grid_m = (M + 127) / 128;

    // ---- layer 1 ----
    gather_kernel<1><<<gat_blocks, 256>>>((const float4*)x, C_IN / 4,
                                          (float4*)agg, C_IN / 4, C_IN / 4,
                                          rowptr, csr, inv, M);
    gemm_mma<<<dim3(2, grid_m), 256>>>(agg, C_IN, x, C_IN,
                                       Wl1, Wr1, h1, C_HID, M, C_HID, 1);

    // ---- layer 2 ----
    gather_kernel<2><<<gat_blocks, 256>>>((const float4*)h1, C_HID / 4,
                                          (float4*)agg, C_HID / 4, C_HID / 4,
                                          rowptr, csr, inv, M);
    gemm_mma<<<dim3(2, grid_m), 256>>>(agg, C_HID, h1, C_HID,
                                       Wl2, Wr2, h2, C_HID, M, C_HID, 1);

    // ---- layer 3: transform-first ----
    pack_w3_kernel<<<96, 256>>>(Wl3, Wr3, W3);
    gemm_mma<<<dim3(1, grid_m), 256>>>(h2, C_HID, h2, 0,
                                       W3, (const float*)nullptr, zr, 128, M, 96, 0);
    gather_kernel<1><<<gat_blocks, 256>>>((const float4*)zr, 128 / 4,
                                          (float4*)agg3, 48 / 4, 48 / 4,
                                          rowptr, csr, inv, M);

    dim3 blk(32, 8);
    final_kernel<<<(M + 7) / 8, blk>>>(agg3, zr, out, M);
}

// round 5
// speedup vs baseline: 2.2931x; 1.6375x over previous
#include <cuda_runtime.h>
#include <cstdint>
#include <math_constants.h>

// ---------------- problem constants ----------------
#define NNODES 50000
#define NEDGES 600000
#define C_IN   128
#define C_HID  256
#define C_OUT  47

// ---------------- static scratch (no allocation allowed) ----------------
__device__ __align__(128) float g_agg [(size_t)NNODES * C_HID];
__device__ __align__(128) float g_h1  [(size_t)NNODES * C_HID];
__device__ __align__(128) float g_h2  [(size_t)NNODES * C_HID];
__device__ __align__(128) float g_zr  [(size_t)NNODES * 128];   // cols 0..46 z, 47..93 r
__device__ __align__(128) float g_agg3[(size_t)NNODES * 48];
__device__ __align__(128) float g_inv [NNODES];
__device__ __align__(128) float g_W3  [96 * 256];
__device__ __align__(128) int   g_cnt [NNODES];
__device__ __align__(128) int   g_rowptr[NNODES + 1];
__device__ __align__(128) int   g_cursor[NNODES];
__device__ __align__(128) int   g_csr [NEDGES];
__device__ __align__(128) int   g_bsum[512];
__device__ int g_is64;

// ---------------- small helpers ----------------
__device__ __forceinline__ long long get_idx(const void* ei, long long i, int is64) {
    if (is64) return ((const long long*)ei)[i];
    return (long long)((const int*)ei)[i];
}

__global__ void detect_kernel(const int* ei32) {
    int bad = 0;
    for (int i = 2 * threadIdx.x + 1; i < 4096; i += 512) bad |= ei32[i];
    int any = __syncthreads_or(bad);
    if (threadIdx.x == 0) g_is64 = (any == 0) ? 1 : 0;
}

__global__ void zero_int_kernel(int* p, int n) {
    int i = blockIdx.x * blockDim.x + threadIdx.x;
    if (i < n) p[i] = 0;
}

__global__ void hist_kernel(const void* __restrict__ ei, int E, int* __restrict__ cnt) {
    int e = blockIdx.x * blockDim.x + threadIdx.x;
    if (e >= E) return;
    int is64 = g_is64;
    long long d = get_idx(ei, (long long)E + e, is64);
    atomicAdd(&cnt[d], 1);
}

// ---- hierarchical scan: block sums -> scan sums -> per-block scan ----
__global__ void blocksum_kernel(const int* __restrict__ cnt, int* __restrict__ bsum, int M) {
    __shared__ int s[8];
    int i = blockIdx.x * 256 + threadIdx.x;
    int v = (i < M) ? cnt[i] : 0;
#pragma unroll
    for (int o = 16; o > 0; o >>= 1) v += __shfl_xor_sync(0xffffffffu, v, o);
    if ((threadIdx.x & 31) == 0) s[threadIdx.x >> 5] = v;
    __syncthreads();
    if (threadIdx.x == 0) {
        int t = 0;
#pragma unroll
        for (int w = 0; w < 8; w++) t += s[w];
        bsum[blockIdx.x] = t;
    }
}

__global__ void scanb_kernel(int* bsum, int nb) {   // exclusive, in place; nb <= 512
    __shared__ int s[512];
    int t = threadIdx.x;
    int v = (t < nb) ? bsum[t] : 0;
    s[t] = v;
    __syncthreads();
    for (int off = 1; off < 512; off <<= 1) {
        int u = (t >= off) ? s[t - off] : 0;
        __syncthreads();
        s[t] += u;
        __syncthreads();
    }
    if (t < nb) bsum[t] = s[t] - v;   // exclusive
}

__global__ void scan_final_kernel(const int* __restrict__ cnt, const int* __restrict__ bsum,
                                  int* __restrict__ rowptr, int* __restrict__ cursor,
                                  float* __restrict__ inv, int M) {
    __shared__ int s[256];
    int t = threadIdx.x;
    int i = blockIdx.x * 256 + t;
    int c = (i < M) ? cnt[i] : 0;
    s[t] = c;
    __syncthreads();
    for (int off = 1; off < 256; off <<= 1) {
        int u = (t >= off) ? s[t - off] : 0;
        __syncthreads();
        s[t] += u;
        __syncthreads();
    }
    if (i < M) {
        int rp = bsum[blockIdx.x] + s[t] - c;   // exclusive
        rowptr[i] = rp;
        cursor[i] = rp;
        inv[i] = 1.0f / fmaxf((float)c, 1.0f);
        if (i == M - 1) rowptr[M] = rp + c;
    }
}

__global__ void fill_kernel(const void* __restrict__ ei, int E,
                            int* __restrict__ cursor, int* __restrict__ csr) {
    int e = blockIdx.x * blockDim.x + threadIdx.x;
    if (e >= E) return;
    int is64 = g_is64;
    long long s = get_idx(ei, e, is64);
    long long d = get_idx(ei, (long long)E + e, is64);
    int slot = atomicAdd(&cursor[d], 1);
    csr[slot] = (int)s;
}

// ---------------- gather-reduce: one warp per node ----------------
template <int NACC>
__global__ void gather_kernel(const float4* __restrict__ src, int src_ld4,
                              float4* __restrict__ dst, int dst_ld4, int nC4,
                              const int* __restrict__ rowptr, const int* __restrict__ csr,
                              const float* __restrict__ inv, int M) {
    int node = blockIdx.x * (blockDim.x >> 5) + (threadIdx.x >> 5);
    if (node >= M) return;
    int lane = threadIdx.x & 31;
    int beg = rowptr[node], end = rowptr[node + 1];
    float s = inv[node];
    float4 acc[NACC];
    bool act[NACC];
#pragma unroll
    for (int i = 0; i < NACC; i++) {
        acc[i] = make_float4(0.f, 0.f, 0.f, 0.f);
        act[i] = (lane + 32 * i) < nC4;
    }
    int e = beg;
    for (; e + 1 < end; e += 2) {
        const float4* r0 = src + (size_t)csr[e] * src_ld4;
        const float4* r1 = src + (size_t)csr[e + 1] * src_ld4;
#pragma unroll
        for (int i = 0; i < NACC; i++) {
            if (act[i]) {
                float4 v0 = r0[lane + 32 * i];
                float4 v1 = r1[lane + 32 * i];
                acc[i].x += v0.x; acc[i].y += v0.y; acc[i].z += v0.z; acc[i].w += v0.w;
                acc[i].x += v1.x; acc[i].y += v1.y; acc[i].z += v1.z; acc[i].w += v1.w;
            }
        }
    }
    if (e < end) {
        const float4* r0 = src + (size_t)csr[e] * src_ld4;
#pragma unroll
        for (int i = 0; i < NACC; i++) {
            if (act[i]) {
                float4 v0 = r0[lane + 32 * i];
                acc[i].x += v0.x; acc[i].y += v0.y; acc[i].z += v0.z; acc[i].w += v0.w;
            }
        }
    }
    float4* drow = dst + (size_t)node * dst_ld4;
#pragma unroll
    for (int i = 0; i < NACC; i++) {
        if (act[i]) {
            acc[i].x *= s; acc[i].y *= s; acc[i].z *= s; acc[i].w *= s;
            drow[lane + 32 * i] = acc[i];
        }
    }
}

__global__ void pack_w3_kernel(const float* __restrict__ Wl3, const float* __restrict__ Wr3,
                               float* __restrict__ W3) {
    int i = blockIdx.x * blockDim.x + threadIdx.x;
    if (i >= 96 * 256) return;
    int row = i >> 8, k = i & 255;
    float v = 0.f;
    if (row < 47)      v = Wl3[row * 256 + k];
    else if (row < 94) v = Wr3[(row - 47) * 256 + k];
    W3[i] = v;
}

// ---------------- bf16x3 warp-MMA GEMM ----------------
// C[m,n] = sum_k Acat[m,k]*Bcat[n,k]; Acat = [A1 | A2], Bcat = [B1 | B2]
// BM=128, BN=128, BK=16. 8 warps 4(M)x2(N); warp tile 32x64.
// bf16x3: hi*hi + hi*lo + lo*hi, fp32 accumulate, mma.m16n8k16.

#define BROW 10   // u32 stride per row (8 pairs + 2 pad)

__device__ __forceinline__ uint32_t pack_bf16(float e0, float e1) {
    uint32_t r;
    asm("cvt.rn.bf16x2.f32 %0, %1, %2;" : "=r"(r) : "f"(e1), "f"(e0));  // e0 -> low half
    return r;
}

__device__ __forceinline__ void mma_bf16(float* c, uint32_t a0, uint32_t a1, uint32_t a2, uint32_t a3,
                                         uint32_t b0, uint32_t b1) {
    asm volatile(
        "mma.sync.aligned.m16n8k16.row.col.f32.bf16.bf16.f32 "
        "{%0,%1,%2,%3}, {%4,%5,%6,%7}, {%8,%9}, {%0,%1,%2,%3};"
        : "+f"(c[0]), "+f"(c[1]), "+f"(c[2]), "+f"(c[3])
        : "r"(a0), "r"(a1), "r"(a2), "r"(a3), "r"(b0), "r"(b1));
}

// split float4 -> hi pairs (2 u32) + lo pairs (2 u32)
__device__ __forceinline__ void split4(float4 v, uint32_t* hi, uint32_t* lo) {
    uint32_t h01 = pack_bf16(v.x, v.y);
    uint32_t h23 = pack_bf16(v.z, v.w);
    float h0 = __uint_as_float(h01 << 16);
    float h1 = __uint_as_float(h01 & 0xffff0000u);
    float h2 = __uint_as_float(h23 << 16);
    float h3 = __uint_as_float(h23 & 0xffff0000u);
    hi[0] = h01; hi[1] = h23;
    lo[0] = pack_bf16(v.x - h0, v.y - h1);
    lo[1] = pack_bf16(v.z - h2, v.w - h3);
}

__global__ void __launch_bounds__(256, 2)
gemm_bf16(const float* __restrict__ A1, int K1,
          const float* __restrict__ A2, int K2,
          const float* __restrict__ B1, const float* __restrict__ B2,
          float* __restrict__ C, int ldc, int M, int N, int do_relu) {
    __shared__ uint32_t Ah[128 * BROW];
    __shared__ uint32_t Al[128 * BROW];
    __shared__ uint32_t Bh[128 * BROW];
    __shared__ uint32_t Bl[128 * BROW];

    const int tid = threadIdx.x;
    const int wid = tid >> 5;
    const int lid = tid & 31;
    const int gID = lid >> 2;
    const int tig = lid & 3;
    const int warp_m = wid & 3;
    const int warp_n = wid >> 2;
    const int m_base = blockIdx.y * 128;
    const int n_base = blockIdx.x * 128;
    const int K = K1 + K2;

    float acc[2][8][4];
#pragma unroll
    for (int mi = 0; mi < 2; mi++)
#pragma unroll
        for (int ni = 0; ni < 8; ni++)
#pragma unroll
            for (int j = 0; j < 4; j++) acc[mi][ni][j] = 0.f;

    for (int kg0 = 0; kg0 < K; kg0 += 16) {
        // ---- A tile: 128 x 16 floats -> bf16 pairs ----
        {
            const float* Asrc; int lda;
            if (kg0 < K1) { Asrc = A1 + kg0; lda = K1; }
            else          { Asrc = A2 + (kg0 - K1); lda = K2; }
#pragma unroll
            for (int t = 0; t < 2; t++) {
                int idx = t * 256 + tid;
                int row = idx >> 2, c4 = (idx & 3) * 4;   // float offset
                int mg = m_base + row;
                float4 v = make_float4(0.f, 0.f, 0.f, 0.f);
                if (mg < M) v = *(const float4*)(Asrc + (size_t)mg * lda + c4);
                uint32_t hi[2], lo[2];
                split4(v, hi, lo);
                int o = row * BROW + (c4 >> 1);
                Ah[o] = hi[0]; Ah[o + 1] = hi[1];
                Al[o] = lo[0]; Al[o + 1] = lo[1];
            }
        }
        // ---- B tile ----
        {
            const float* Bsrc; int ldb;
            if (kg0 < K1) { Bsrc = B1 + kg0; ldb = K1; }
            else          { Bsrc = B2 + (kg0 - K1); ldb = K2; }
#pragma unroll
            for (int t = 0; t < 2; t++) {
                int idx = t * 256 + tid;
                int row = idx >> 2, c4 = (idx & 3) * 4;
                int ng = n_base + row;
                float4 v = make_float4(0.f, 0.f, 0.f, 0.f);
                if (ng < N) v = *(const float4*)(Bsrc + (size_t)ng * ldb + c4);
                uint32_t hi[2], lo[2];
                split4(v, hi, lo);
                int o = row * BROW + (c4 >> 1);
                Bh[o] = hi[0]; Bh[o + 1] = hi[1];
                Bl[o] = lo[0]; Bl[o + 1] = lo[1];
            }
        }
        __syncthreads();

        // ---- MMA: one k16 step per chunk ----
        uint32_t ah[2][4], al[2][4];
#pragma unroll
        for (int mi = 0; mi < 2; mi++) {
            int rm = warp_m * 32 + mi * 16;
            int r0 = (rm + gID) * BROW + tig;
            int r1 = (rm + gID + 8) * BROW + tig;
            ah[mi][0] = Ah[r0];     ah[mi][1] = Ah[r1];
            ah[mi][2] = Ah[r0 + 4]; ah[mi][3] = Ah[r1 + 4];
            al[mi][0] = Al[r0];     al[mi][1] = Al[r1];
            al[mi][2] = Al[r0 + 4]; al[mi][3] = Al[r1 + 4];
        }
#pragma unroll
        for (int ni = 0; ni < 8; ni++) {
            int nn = warp_n * 64 + ni * 8 + gID;
            int o = nn * BROW + tig;
            uint32_t bh0 = Bh[o], bh1 = Bh[o + 4];
            uint32_t bl0 = Bl[o], bl1 = Bl[o + 4];
#pragma unroll
            for (int mi = 0; mi < 2; mi++) {
                mma_bf16(acc[mi][ni], ah[mi][0], ah[mi][1], ah[mi][2], ah[mi][3], bh0, bh1);
                mma_bf16(acc[mi][ni], ah[mi][0], ah[mi][1], ah[mi][2], ah[mi][3], bl0, bl1);
                mma_bf16(acc[mi][ni], al[mi][0], al[mi][1], al[mi][2], al[mi][3], bh0, bh1);
            }
        }
        __syncthreads();
    }

    // ---- epilogue ----
#pragma unroll
    for (int mi = 0; mi < 2; mi++) {
#pragma unroll
        for (int ni = 0; ni < 8; ni++) {
            int col = n_base + warp_n * 64 + ni * 8 + 2 * tig;
            if (col >= N) continue;
            int r0 = m_base + warp_m * 32 + mi * 16 + gID;
            int r1 = r0 + 8;
            float2 v0 = make_float2(acc[mi][ni][0], acc[mi][ni][1]);
            float2 v1 = make_float2(acc[mi][ni][2], acc[mi][ni][3]);
            if (do_relu) {
                v0.x = fmaxf(v0.x, 0.f); v0.y = fmaxf(v0.y, 0.f);
                v1.x = fmaxf(v1.x, 0.f); v1.y = fmaxf(v1.y, 0.f);
            }
            if (r0 < M) *(float2*)(C + (size_t)r0 * ldc + col) = v0;
            if (r1 < M) *(float2*)(C + (size_t)r1 * ldc + col) = v1;
        }
    }
}

// ---------------- final: out = log_softmax(agg3 + r) (inv already applied) ----------------
__global__ void final_kernel(const float* __restrict__ agg3, const float* __restrict__ zr,
                             float* __restrict__ out, int M) {
    int m = blockIdx.x * blockDim.y + threadIdx.y;
    if (m >= M) return;
    int lane = threadIdx.x;
    float v1 = -CUDART_INF_F, v2 = -CUDART_INF_F;
    if (lane < 47)
        v1 = agg3[(size_t)m * 48 + lane] + zr[(size_t)m * 128 + 47 + lane];
    int c2 = lane + 32;
    if (c2 < 47)
        v2 = agg3[(size_t)m * 48 + c2] + zr[(size_t)m * 128 + 47 + c2];
    float mx = fmaxf(v1, v2);
#pragma unroll
    for (int o = 16; o > 0; o >>= 1) mx = fmaxf(mx, __shfl_xor_sync(0xffffffffu, mx, o));
    float s = 0.f;
    if (lane < 47) s += expf(v1 - mx);
    if (c2 < 47)   s += expf(v2 - mx);
#pragma unroll
    for (int o = 16; o > 0; o >>= 1) s += __shfl_xor_sync(0xffffffffu, s, o);
    float lse = logf(s);
    if (lane < 47) out[(size_t)m * 47 + lane] = v1 - mx - lse;
    if (c2 < 47)   out[(size_t)m * 47 + c2]   = v2 - mx - lse;
}

// ---------------- launch ----------------
extern "C" void kernel_launch(void* const* d_in, const int* in_sizes, int n_in,
                              void* d_out, int out_size) {
    const float* x   = (const float*)d_in[0];
    const float* Wl1 = (const float*)d_in[1];
    const float* Wr1 = (const float*)d_in[2];
    const float* Wl2 = (const float*)d_in[3];
    const float* Wr2 = (const float*)d_in[4];
    const float* Wl3 = (const float*)d_in[5];
    const float* Wr3 = (const float*)d_in[6];
    const void*  ei  = d_in[7];
    const int E = in_sizes[7] / 2;
    const int M = in_sizes[0] / C_IN;
    float* out = (float*)d_out;

    float *agg, *h1, *h2, *zr, *agg3, *inv, *W3;
    int *cnt, *rowptr, *cursor, *csr, *bsum;
    cudaGetSymbolAddress((void**)&agg,    g_agg);
    cudaGetSymbolAddress((void**)&h1,     g_h1);
    cudaGetSymbolAddress((void**)&h2,     g_h2);
    cudaGetSymbolAddress((void**)&zr,     g_zr);
    cudaGetSymbolAddress((void**)&agg3,   g_agg3);
    cudaGetSymbolAddress((void**)&inv,    g_inv);
    cudaGetSymbolAddress((void**)&W3,     g_W3);
    cudaGetSymbolAddress((void**)&cnt,    g_cnt);
    cudaGetSymbolAddress((void**)&rowptr, g_rowptr);
    cudaGetSymbolAddress((void**)&cursor, g_cursor);
    cudaGetSymbolAddress((void**)&csr,    g_csr);
    cudaGetSymbolAddress((void**)&bsum,   g_bsum);

    detect_kernel<<<1, 256>>>((const int*)ei);

    // ---- CSR build ----
    const int nb = (M + 255) / 256;
    zero_int_kernel<<<nb, 256>>>(cnt, M);
    hist_kernel<<<(E + 255) / 256, 256>>>(ei, E, cnt);
    blocksum_kernel<<<nb, 256>>>(cnt, bsum, M);
    scanb_kernel<<<1, 512>>>(bsum, nb);
    scan_final_kernel<<<nb, 256>>>(cnt, bsum, rowptr, cursor, inv, M);
    fill_kernel<<<(E + 255) / 256, 256>>>(ei, E, cursor, csr);

    const int gat_blocks = (M + 7) / 8;
    const int grid_m = (M + 127) / 128;

    // ---- layer 1 ----
    gather_kernel<1><<<gat_blocks, 256>>>((const float4*)x, C_IN / 4,
                                          (float4*)agg, C_IN / 4, C_IN / 4,
                                          rowptr, csr, inv, M);
    gemm_bf16<<<dim3(2, grid_m), 256>>>(agg, C_IN, x, C_IN,
                                        Wl1, Wr1, h1, C_HID, M, C_HID, 1);

    // ---- layer 2 ----
    gather_kernel<2><<<gat_blocks, 256>>>((const float4*)h1, C_HID / 4,
                                          (float4*)agg, C_HID / 4, C_HID / 4,
                                          rowptr, csr, inv, M);
    gemm_bf16<<<dim3(2, grid_m), 256>>>(agg, C_HID, h1, C_HID,
                                        Wl2, Wr2, h2, C_HID, M, C_HID, 1);

    // ---- layer 3: transform-first ----
    pack_w3_kernel<<<96, 256>>>(Wl3, Wr3, W3);
    gemm_bf16<<<dim3(1, grid_m), 256>>>(h2, C_HID, h2, 0,
                                        W3, (const float*)nullptr, zr, 128, M, 96, 0);
    gather_kernel<1><<<gat_blocks, 256>>>((const float4*)zr, 128 / 4,
                                          (float4*)agg3, 48 / 4, 48 / 4,
                                          rowptr, csr, inv, M);

    dim3 blk(32, 8);
    final_kernel<<<(M + 7) / 8, blk>>>(agg3, zr, out, M);
}